// round 1
// baseline (speedup 1.0000x reference)
#include <cuda_runtime.h>
#include <cstdint>

#define BATCH 2
#define SEQ 2048
#define DIM 512
#define INNER 512
#define N_HEAD 8
#define HEAD_DIM 64
#define ATT_T 1e-4f
#define SCALE_F 0.125f

#define QS 68   // padded smem row stride (68*4B = 272B = 17*16B -> float4 aligned)

// scratch (allocation-free rule: __device__ globals)
__device__ float g_Q[BATCH * SEQ * INNER];
__device__ float g_K[BATCH * SEQ * INNER];
__device__ float g_V[BATCH * SEQ * INNER];
__device__ float g_O[BATCH * SEQ * INNER];

// ---------------------------------------------------------------------------
// Tiled fp32 GEMM: C[M,N] = A[M,K] @ B[K,N] (+ bias). 64x64 tile, BK=16,
// 256 threads, 4x4 per-thread micro-tile, float4 smem loads.
// ---------------------------------------------------------------------------
__global__ void __launch_bounds__(256) gemm64(
    const float* __restrict__ A, const float* __restrict__ B,
    const float* __restrict__ bias, float* __restrict__ C,
    int M, int N, int K)
{
    __shared__ float As[16][QS];   // As[k][m] (transposed)
    __shared__ float Bs[16][QS];   // Bs[k][n]

    const int tid = threadIdx.x;
    const int tx = tid & 15, ty = tid >> 4;
    const int bn = blockIdx.x * 64, bm = blockIdx.y * 64;

    float acc[4][4] = {};

    for (int kt = 0; kt < K; kt += 16) {
        {
            int r = tid >> 2;            // 0..63
            int c = (tid & 3) << 2;      // 0,4,8,12
            float4 v = *(const float4*)&A[(size_t)(bm + r) * K + kt + c];
            As[c + 0][r] = v.x; As[c + 1][r] = v.y;
            As[c + 2][r] = v.z; As[c + 3][r] = v.w;
        }
        {
            int r = tid >> 4;            // 0..15
            int c = (tid & 15) << 2;     // 0..60
            *(float4*)&Bs[r][c] = *(const float4*)&B[(size_t)(kt + r) * N + bn + c];
        }
        __syncthreads();
        #pragma unroll
        for (int k = 0; k < 16; k++) {
            float4 a4 = *(const float4*)&As[k][ty << 2];
            float4 b4 = *(const float4*)&Bs[k][tx << 2];
            float av[4] = {a4.x, a4.y, a4.z, a4.w};
            float bv[4] = {b4.x, b4.y, b4.z, b4.w};
            #pragma unroll
            for (int i = 0; i < 4; i++)
                #pragma unroll
                for (int j = 0; j < 4; j++)
                    acc[i][j] += av[i] * bv[j];
        }
        __syncthreads();
    }

    #pragma unroll
    for (int i = 0; i < 4; i++) {
        int row = bm + (ty << 2) + i;
        int col = bn + (tx << 2);
        float4 o;
        o.x = acc[i][0]; o.y = acc[i][1]; o.z = acc[i][2]; o.w = acc[i][3];
        if (bias) {
            o.x += bias[col]; o.y += bias[col + 1];
            o.z += bias[col + 2]; o.w += bias[col + 3];
        }
        *(float4*)&C[(size_t)row * N + col] = o;
    }
}

// ---------------------------------------------------------------------------
// Attention: one block = (b, h, 64-query tile). Two passes over keys:
//   pass 1: online max m and denom Z per query row
//   pass 2: w = relu(exp(s - m) - t*Z), O = sum w*V / sum w
// Clip identity: softmax-clip-renorm == relu(e - t*Z)/sum(relu(e - t*Z)).
// ---------------------------------------------------------------------------
__global__ void __launch_bounds__(256) attn_kernel()
{
    extern __shared__ float sm[];
    float* Qs = sm;                 // [64][QS]  Qs[d][q]   (transposed)
    float* Ks = sm + 64 * QS;       // [64][QS]  Ks[d][k]   (transposed)
    float* Vs = sm + 2 * 64 * QS;   // [64][QS]  Vs[k][d]
    float* Ws = sm + 3 * 64 * QS;   // [64][QS]  Ws[k][q]

    const int tid = threadIdx.x;
    const int tx = tid & 15, ty = tid >> 4;
    const int qt = blockIdx.x, h = blockIdx.y, b = blockIdx.z;
    const int q0 = qt * 64;

    const size_t baseQ  = ((size_t)b * SEQ + q0) * INNER + h * HEAD_DIM;
    const size_t baseKV = ((size_t)b * SEQ) * INNER + h * HEAD_DIM;

    // load Q tile transposed: Qs[d][q]
    #pragma unroll
    for (int i = 0; i < 4; i++) {
        int idx = tid + 256 * i;          // 0..1023
        int row = idx >> 4;               // query 0..63
        int c   = (idx & 15) << 2;        // d 0..60
        float4 v = *(const float4*)&g_Q[baseQ + (size_t)row * INNER + c];
        Qs[(c + 0) * QS + row] = v.x; Qs[(c + 1) * QS + row] = v.y;
        Qs[(c + 2) * QS + row] = v.z; Qs[(c + 3) * QS + row] = v.w;
    }

    float m[4], l[4];
    #pragma unroll
    for (int i = 0; i < 4; i++) { m[i] = -__int_as_float(0x7f800000); l[i] = 0.f; }

    // ---------------- pass 1: m, Z ----------------
    for (int kt = 0; kt < SEQ / 64; kt++) {
        __syncthreads();
        #pragma unroll
        for (int i = 0; i < 4; i++) {
            int idx = tid + 256 * i;
            int row = idx >> 4;
            int c   = (idx & 15) << 2;
            float4 v = *(const float4*)&g_K[baseKV + (size_t)(kt * 64 + row) * INNER + c];
            Ks[(c + 0) * QS + row] = v.x; Ks[(c + 1) * QS + row] = v.y;
            Ks[(c + 2) * QS + row] = v.z; Ks[(c + 3) * QS + row] = v.w;
        }
        __syncthreads();

        float acc[4][4] = {};
        #pragma unroll 4
        for (int d = 0; d < 64; d++) {
            float4 a4 = *(const float4*)&Qs[d * QS + (ty << 2)];
            float4 b4 = *(const float4*)&Ks[d * QS + (tx << 2)];
            float av[4] = {a4.x, a4.y, a4.z, a4.w};
            float bv[4] = {b4.x, b4.y, b4.z, b4.w};
            #pragma unroll
            for (int i = 0; i < 4; i++)
                #pragma unroll
                for (int j = 0; j < 4; j++)
                    acc[i][j] += av[i] * bv[j];
        }

        #pragma unroll
        for (int qi = 0; qi < 4; qi++) {
            float mt = fmaxf(fmaxf(acc[qi][0], acc[qi][1]),
                             fmaxf(acc[qi][2], acc[qi][3])) * SCALE_F;
            #pragma unroll
            for (int o = 1; o < 16; o <<= 1)
                mt = fmaxf(mt, __shfl_xor_sync(0xffffffffu, mt, o));
            float mn = fmaxf(m[qi], mt);
            float p = 0.f;
            #pragma unroll
            for (int ki = 0; ki < 4; ki++)
                p += __expf(acc[qi][ki] * SCALE_F - mn);
            #pragma unroll
            for (int o = 1; o < 16; o <<= 1)
                p += __shfl_xor_sync(0xffffffffu, p, o);
            l[qi] = l[qi] * __expf(m[qi] - mn) + p;
            m[qi] = mn;
        }
    }

    float thr[4];
    #pragma unroll
    for (int qi = 0; qi < 4; qi++) thr[qi] = ATT_T * l[qi];

    float oacc[4][4] = {};
    float wsum[4] = {};

    // ---------------- pass 2: weights + O ----------------
    for (int kt = 0; kt < SEQ / 64; kt++) {
        __syncthreads();
        #pragma unroll
        for (int i = 0; i < 4; i++) {
            int idx = tid + 256 * i;
            int row = idx >> 4;
            int c   = (idx & 15) << 2;
            size_t goff = baseKV + (size_t)(kt * 64 + row) * INNER + c;
            float4 v = *(const float4*)&g_K[goff];
            Ks[(c + 0) * QS + row] = v.x; Ks[(c + 1) * QS + row] = v.y;
            Ks[(c + 2) * QS + row] = v.z; Ks[(c + 3) * QS + row] = v.w;
            *(float4*)&Vs[row * QS + c] = *(const float4*)&g_V[goff];
        }
        __syncthreads();

        float acc[4][4] = {};
        #pragma unroll 4
        for (int d = 0; d < 64; d++) {
            float4 a4 = *(const float4*)&Qs[d * QS + (ty << 2)];
            float4 b4 = *(const float4*)&Ks[d * QS + (tx << 2)];
            float av[4] = {a4.x, a4.y, a4.z, a4.w};
            float bv[4] = {b4.x, b4.y, b4.z, b4.w};
            #pragma unroll
            for (int i = 0; i < 4; i++)
                #pragma unroll
                for (int j = 0; j < 4; j++)
                    acc[i][j] += av[i] * bv[j];
        }

        #pragma unroll
        for (int qi = 0; qi < 4; qi++) {
            #pragma unroll
            for (int ki = 0; ki < 4; ki++) {
                float w = fmaxf(__expf(acc[qi][ki] * SCALE_F - m[qi]) - thr[qi], 0.f);
                wsum[qi] += w;
                Ws[((tx << 2) + ki) * QS + (ty << 2) + qi] = w;
            }
        }
        __syncthreads();

        #pragma unroll 4
        for (int k = 0; k < 64; k++) {
            float4 a4 = *(const float4*)&Ws[k * QS + (ty << 2)];
            float4 b4 = *(const float4*)&Vs[k * QS + (tx << 2)];
            float av[4] = {a4.x, a4.y, a4.z, a4.w};
            float bv[4] = {b4.x, b4.y, b4.z, b4.w};
            #pragma unroll
            for (int i = 0; i < 4; i++)
                #pragma unroll
                for (int j = 0; j < 4; j++)
                    oacc[i][j] += av[i] * bv[j];
        }
    }

    // reduce wsum across the 16 key-lanes, then normalize + write O
    #pragma unroll
    for (int qi = 0; qi < 4; qi++) {
        #pragma unroll
        for (int o = 1; o < 16; o <<= 1)
            wsum[qi] += __shfl_xor_sync(0xffffffffu, wsum[qi], o);
        float inv = 1.f / wsum[qi];
        float4 ov;
        ov.x = oacc[qi][0] * inv; ov.y = oacc[qi][1] * inv;
        ov.z = oacc[qi][2] * inv; ov.w = oacc[qi][3] * inv;
        *(float4*)&g_O[baseQ + (size_t)((ty << 2) + qi) * INNER + (tx << 2)] = ov;
    }
}

// ---------------------------------------------------------------------------
extern "C" void kernel_launch(void* const* d_in, const int* in_sizes, int n_in,
                              void* d_out, int out_size)
{
    const float* fr = (const float*)d_in[0];
    const float* dt = (const float*)d_in[1];
    const float* Wq = (const float*)d_in[2];
    const float* Wk = (const float*)d_in[3];
    const float* Wv = (const float*)d_in[4];
    const float* Wo = (const float*)d_in[5];
    const float* bo = (const float*)d_in[6];
    float* out = (float*)d_out;

    float *pQ, *pK, *pV, *pO;
    cudaGetSymbolAddress((void**)&pQ, g_Q);
    cudaGetSymbolAddress((void**)&pK, g_K);
    cudaGetSymbolAddress((void**)&pV, g_V);
    cudaGetSymbolAddress((void**)&pO, g_O);

    const int M = BATCH * SEQ;   // 4096

    dim3 gp(INNER / 64, M / 64);
    gemm64<<<gp, 256>>>(fr, Wq, nullptr, pQ, M, INNER, DIM);
    gemm64<<<gp, 256>>>(dt, Wk, nullptr, pK, M, INNER, DIM);
    gemm64<<<gp, 256>>>(dt, Wv, nullptr, pV, M, INNER, DIM);

    const int smem = 4 * 64 * QS * (int)sizeof(float);  // 69632 B
    cudaFuncSetAttribute(attn_kernel,
                         cudaFuncAttributeMaxDynamicSharedMemorySize, smem);
    attn_kernel<<<dim3(SEQ / 64, N_HEAD, BATCH), 256, smem>>>();

    dim3 go(DIM / 64, M / 64);
    gemm64<<<go, 256>>>(pO, Wo, bo, out, M, DIM, INNER);
}

// round 2
// speedup vs baseline: 1.1225x; 1.1225x over previous
#include <cuda_runtime.h>
#include <cstdint>

#define BATCH 2
#define SEQ 2048
#define DIM 512
#define INNER 512
#define N_HEAD 8
#define HEAD_DIM 64
#define ATT_T 1e-4f
#define SCALE_F 0.125f

typedef unsigned long long ull;

// scratch (allocation-free rule: __device__ globals)
__device__ float g_Q[BATCH * SEQ * INNER];
__device__ float g_K[BATCH * SEQ * INNER];
__device__ float g_V[BATCH * SEQ * INNER];
__device__ float g_O[BATCH * SEQ * INNER];

// ---------------- packed f32x2 helpers (ptxas never emits FFMA2 from C++) ---
static __device__ __forceinline__ ull pk2(float lo, float hi) {
    ull d;
    asm("mov.b64 %0, {%1, %2};" : "=l"(d)
        : "r"(__float_as_uint(lo)), "r"(__float_as_uint(hi)));
    return d;
}
static __device__ __forceinline__ ull dup2f(float x) {
    ull d;
    unsigned u = __float_as_uint(x);
    asm("mov.b64 %0, {%1, %1};" : "=l"(d) : "r"(u));
    return d;
}
static __device__ __forceinline__ void fma2(ull& d, ull a, ull b) {
    asm("fma.rn.f32x2 %0, %1, %2, %0;" : "+l"(d) : "l"(a), "l"(b));
}
static __device__ __forceinline__ float2 up2(ull v) {
    unsigned lo, hi;
    asm("mov.b64 {%0, %1}, %2;" : "=r"(lo), "=r"(hi) : "l"(v));
    return make_float2(__uint_as_float(lo), __uint_as_float(hi));
}

// ---------------------------------------------------------------------------
// Tiled fp32 GEMM (FFMA2): C[M,N] = A[M,K] @ B[K,N] (+ bias).
// 64x64 tile, BK=16, 256 threads, 4x4 micro-tile packed along N.
// ---------------------------------------------------------------------------
#define GQS 68
__global__ void __launch_bounds__(256) gemm64(
    const float* __restrict__ A, const float* __restrict__ B,
    const float* __restrict__ bias, float* __restrict__ C,
    int M, int N, int K)
{
    __shared__ float As[16][GQS];   // As[k][m] (transposed)
    __shared__ float Bs[16][GQS];   // Bs[k][n]

    const int tid = threadIdx.x;
    const int tx = tid & 15, ty = tid >> 4;
    const int bn = blockIdx.x * 64, bm = blockIdx.y * 64;

    ull acc2[4][2];
    #pragma unroll
    for (int i = 0; i < 4; i++) { acc2[i][0] = 0ull; acc2[i][1] = 0ull; }

    for (int kt = 0; kt < K; kt += 16) {
        {
            int r = tid >> 2;
            int c = (tid & 3) << 2;
            float4 v = *(const float4*)&A[(size_t)(bm + r) * K + kt + c];
            As[c + 0][r] = v.x; As[c + 1][r] = v.y;
            As[c + 2][r] = v.z; As[c + 3][r] = v.w;
        }
        {
            int r = tid >> 4;
            int c = (tid & 15) << 2;
            *(float4*)&Bs[r][c] = *(const float4*)&B[(size_t)(kt + r) * N + bn + c];
        }
        __syncthreads();
        #pragma unroll
        for (int k = 0; k < 16; k++) {
            float4 a4 = *(const float4*)&As[k][ty << 2];
            float4 b4 = *(const float4*)&Bs[k][tx << 2];
            ull bp0 = pk2(b4.x, b4.y), bp1 = pk2(b4.z, b4.w);
            float av[4] = {a4.x, a4.y, a4.z, a4.w};
            #pragma unroll
            for (int i = 0; i < 4; i++) {
                ull ad = dup2f(av[i]);
                fma2(acc2[i][0], ad, bp0);
                fma2(acc2[i][1], ad, bp1);
            }
        }
        __syncthreads();
    }

    #pragma unroll
    for (int i = 0; i < 4; i++) {
        int row = bm + (ty << 2) + i;
        int col = bn + (tx << 2);
        float2 p0 = up2(acc2[i][0]), p1 = up2(acc2[i][1]);
        float4 o = {p0.x, p0.y, p1.x, p1.y};
        if (bias) {
            o.x += bias[col]; o.y += bias[col + 1];
            o.z += bias[col + 2]; o.w += bias[col + 3];
        }
        *(float4*)&C[(size_t)row * N + col] = o;
    }
}

// ---------------------------------------------------------------------------
// Attention: block = (b, h, 128-query tile); 256 threads = 16(q) x 16(k).
// 8x8 micro-tile, FFMA2-packed. Two passes:
//   pass 1: online (m, Z) per query row
//   pass 2: w = relu(exp(s-m) - t*Z); O = sum w*V / sum w
// Clip identity: softmax-clip-renorm == relu(e - t*Z)/sum(relu(e - t*Z)).
// ---------------------------------------------------------------------------
#define TQ 128
#define TK 128
#define QS1 132   // stride for Qs/Ks rows (128 + 4 pad, 16B-aligned)
#define VS1 68    // stride for Vs rows (64 + 4 pad)
#define NKT (SEQ / TK)

__global__ void __launch_bounds__(256, 1) attn_kernel()
{
    extern __shared__ float sm[];
    float* Qs = sm;                            // [64][QS1]  Qs[d][q]
    float* Ks = sm + 64 * QS1;                 // [64][QS1]  Ks[d][k]
    float* Vs = sm + 2 * 64 * QS1;             // [128][VS1] Vs[k][d]
    float* Ws = sm + 2 * 64 * QS1 + TK * VS1;  // [128][128] Ws[k][q] XOR-swizzled

    const int tid = threadIdx.x;
    const int tx = tid & 15, ty = tid >> 4;
    const int tx8 = tx << 3, ty8 = ty << 3, tx4 = tx << 2;
    const int qt = blockIdx.x, h = blockIdx.y, b = blockIdx.z;

    const size_t baseQ  = ((size_t)b * SEQ + qt * TQ) * INNER + h * HEAD_DIM;
    const size_t baseKV = ((size_t)b * SEQ) * INNER + h * HEAD_DIM;

    // load Q tile transposed: Qs[d][q]
    #pragma unroll
    for (int i = 0; i < 8; i++) {
        int idx = tid + 256 * i;              // 0..2047
        int row = idx >> 4;                   // q 0..127
        int c   = (idx & 15) << 2;            // d 0,4..60
        float4 v = *(const float4*)&g_Q[baseQ + (size_t)row * INNER + c];
        Qs[(c + 0) * QS1 + row] = v.x; Qs[(c + 1) * QS1 + row] = v.y;
        Qs[(c + 2) * QS1 + row] = v.z; Qs[(c + 3) * QS1 + row] = v.w;
    }

    float m[8], l[8];
    #pragma unroll
    for (int i = 0; i < 8; i++) { m[i] = -__int_as_float(0x7f800000); l[i] = 0.f; }

    // ---------------- pass 1: m, Z ----------------
    for (int kt = 0; kt < NKT; kt++) {
        __syncthreads();
        #pragma unroll
        for (int i = 0; i < 8; i++) {
            int idx = tid + 256 * i;
            int row = idx >> 4;
            int c   = (idx & 15) << 2;
            float4 v = *(const float4*)&g_K[baseKV + (size_t)(kt * TK + row) * INNER + c];
            Ks[(c + 0) * QS1 + row] = v.x; Ks[(c + 1) * QS1 + row] = v.y;
            Ks[(c + 2) * QS1 + row] = v.z; Ks[(c + 3) * QS1 + row] = v.w;
        }
        __syncthreads();

        ull acc2[8][4];
        #pragma unroll
        for (int i = 0; i < 8; i++)
            #pragma unroll
            for (int j = 0; j < 4; j++) acc2[i][j] = 0ull;

        #pragma unroll 2
        for (int d = 0; d < 64; d++) {
            const float* qr = &Qs[d * QS1 + ty8];
            const float* kr = &Ks[d * QS1 + tx8];
            float4 a0 = *(const float4*)qr, a1 = *(const float4*)(qr + 4);
            float4 b0 = *(const float4*)kr, b1 = *(const float4*)(kr + 4);
            ull bp[4] = {pk2(b0.x, b0.y), pk2(b0.z, b0.w),
                         pk2(b1.x, b1.y), pk2(b1.z, b1.w)};
            float av[8] = {a0.x, a0.y, a0.z, a0.w, a1.x, a1.y, a1.z, a1.w};
            #pragma unroll
            for (int i = 0; i < 8; i++) {
                ull ad = dup2f(av[i]);
                fma2(acc2[i][0], ad, bp[0]); fma2(acc2[i][1], ad, bp[1]);
                fma2(acc2[i][2], ad, bp[2]); fma2(acc2[i][3], ad, bp[3]);
            }
        }

        #pragma unroll
        for (int qi = 0; qi < 8; qi++) {
            float sv[8];
            #pragma unroll
            for (int jp = 0; jp < 4; jp++) {
                float2 f = up2(acc2[qi][jp]);
                sv[2 * jp] = f.x * SCALE_F; sv[2 * jp + 1] = f.y * SCALE_F;
            }
            float mt = sv[0];
            #pragma unroll
            for (int k = 1; k < 8; k++) mt = fmaxf(mt, sv[k]);
            #pragma unroll
            for (int o = 1; o < 16; o <<= 1)
                mt = fmaxf(mt, __shfl_xor_sync(0xffffffffu, mt, o));
            float mn = fmaxf(m[qi], mt);
            float p = 0.f;
            #pragma unroll
            for (int k = 0; k < 8; k++) p += __expf(sv[k] - mn);
            #pragma unroll
            for (int o = 1; o < 16; o <<= 1)
                p += __shfl_xor_sync(0xffffffffu, p, o);
            l[qi] = l[qi] * __expf(m[qi] - mn) + p;
            m[qi] = mn;
        }
    }

    float thr[8], wsum[8];
    #pragma unroll
    for (int qi = 0; qi < 8; qi++) { thr[qi] = ATT_T * l[qi]; wsum[qi] = 0.f; }

    ull oacc[8][2];
    #pragma unroll
    for (int i = 0; i < 8; i++) { oacc[i][0] = 0ull; oacc[i][1] = 0ull; }

    // ---------------- pass 2: weights + O ----------------
    for (int kt = 0; kt < NKT; kt++) {
        __syncthreads();
        #pragma unroll
        for (int i = 0; i < 8; i++) {
            int idx = tid + 256 * i;
            int row = idx >> 4;
            int c   = (idx & 15) << 2;
            size_t goff = baseKV + (size_t)(kt * TK + row) * INNER + c;
            float4 v = *(const float4*)&g_K[goff];
            Ks[(c + 0) * QS1 + row] = v.x; Ks[(c + 1) * QS1 + row] = v.y;
            Ks[(c + 2) * QS1 + row] = v.z; Ks[(c + 3) * QS1 + row] = v.w;
            *(float4*)&Vs[row * VS1 + c] = *(const float4*)&g_V[goff];
        }
        __syncthreads();

        ull acc2[8][4];
        #pragma unroll
        for (int i = 0; i < 8; i++)
            #pragma unroll
            for (int j = 0; j < 4; j++) acc2[i][j] = 0ull;

        #pragma unroll 2
        for (int d = 0; d < 64; d++) {
            const float* qr = &Qs[d * QS1 + ty8];
            const float* kr = &Ks[d * QS1 + tx8];
            float4 a0 = *(const float4*)qr, a1 = *(const float4*)(qr + 4);
            float4 b0 = *(const float4*)kr, b1 = *(const float4*)(kr + 4);
            ull bp[4] = {pk2(b0.x, b0.y), pk2(b0.z, b0.w),
                         pk2(b1.x, b1.y), pk2(b1.z, b1.w)};
            float av[8] = {a0.x, a0.y, a0.z, a0.w, a1.x, a1.y, a1.z, a1.w};
            #pragma unroll
            for (int i = 0; i < 8; i++) {
                ull ad = dup2f(av[i]);
                fma2(acc2[i][0], ad, bp[0]); fma2(acc2[i][1], ad, bp[1]);
                fma2(acc2[i][2], ad, bp[2]); fma2(acc2[i][3], ad, bp[3]);
            }
        }

        // weights -> swizzled Ws[k][q]
        #pragma unroll
        for (int qi = 0; qi < 8; qi++) {
            float sv[8];
            #pragma unroll
            for (int jp = 0; jp < 4; jp++) {
                float2 f = up2(acc2[qi][jp]);
                sv[2 * jp] = f.x * SCALE_F; sv[2 * jp + 1] = f.y * SCALE_F;
            }
            int q = ty8 + qi;
            #pragma unroll
            for (int kj = 0; kj < 8; kj++) {
                float w = fmaxf(__expf(sv[kj] - m[qi]) - thr[qi], 0.f);
                wsum[qi] += w;
                int k = tx8 + kj;
                int g = (q >> 2) ^ (k >> 3);
                Ws[k * 128 + (g << 2) + (q & 3)] = w;
            }
        }
        __syncthreads();

        // PV: O[q][d] += W[k][q] * V[k][d]
        #pragma unroll 2
        for (int k = 0; k < TK; k++) {
            int gsw = k >> 3;
            int g0 = (ty * 2) ^ gsw;
            int g1 = (ty * 2 + 1) ^ gsw;
            float4 w0 = *(const float4*)&Ws[k * 128 + (g0 << 2)];
            float4 w1 = *(const float4*)&Ws[k * 128 + (g1 << 2)];
            float4 vv = *(const float4*)&Vs[k * VS1 + tx4];
            ull vp0 = pk2(vv.x, vv.y), vp1 = pk2(vv.z, vv.w);
            float wv[8] = {w0.x, w0.y, w0.z, w0.w, w1.x, w1.y, w1.z, w1.w};
            #pragma unroll
            for (int i = 0; i < 8; i++) {
                ull ad = dup2f(wv[i]);
                fma2(oacc[i][0], ad, vp0);
                fma2(oacc[i][1], ad, vp1);
            }
        }
    }

    // reduce wsum across the 16 key-lanes, normalize, write O
    #pragma unroll
    for (int qi = 0; qi < 8; qi++) {
        #pragma unroll
        for (int o = 1; o < 16; o <<= 1)
            wsum[qi] += __shfl_xor_sync(0xffffffffu, wsum[qi], o);
        float inv = 1.f / wsum[qi];
        float2 o0 = up2(oacc[qi][0]), o1 = up2(oacc[qi][1]);
        float4 ov = {o0.x * inv, o0.y * inv, o1.x * inv, o1.y * inv};
        *(float4*)&g_O[baseQ + (size_t)(ty8 + qi) * INNER + tx4] = ov;
    }
}

// ---------------------------------------------------------------------------
extern "C" void kernel_launch(void* const* d_in, const int* in_sizes, int n_in,
                              void* d_out, int out_size)
{
    const float* fr = (const float*)d_in[0];
    const float* dt = (const float*)d_in[1];
    const float* Wq = (const float*)d_in[2];
    const float* Wk = (const float*)d_in[3];
    const float* Wv = (const float*)d_in[4];
    const float* Wo = (const float*)d_in[5];
    const float* bo = (const float*)d_in[6];
    float* out = (float*)d_out;

    float *pQ, *pK, *pV, *pO;
    cudaGetSymbolAddress((void**)&pQ, g_Q);
    cudaGetSymbolAddress((void**)&pK, g_K);
    cudaGetSymbolAddress((void**)&pV, g_V);
    cudaGetSymbolAddress((void**)&pO, g_O);

    const int M = BATCH * SEQ;   // 4096

    dim3 gp(INNER / 64, M / 64);
    gemm64<<<gp, 256>>>(fr, Wq, nullptr, pQ, M, INNER, DIM);
    gemm64<<<gp, 256>>>(dt, Wk, nullptr, pK, M, INNER, DIM);
    gemm64<<<gp, 256>>>(dt, Wv, nullptr, pV, M, INNER, DIM);

    const int smem = (2 * 64 * QS1 + TK * VS1 + TK * 128) * (int)sizeof(float); // 167936
    cudaFuncSetAttribute(attn_kernel,
                         cudaFuncAttributeMaxDynamicSharedMemorySize, smem);
    attn_kernel<<<dim3(SEQ / TQ, N_HEAD, BATCH), 256, smem>>>();

    dim3 go(DIM / 64, M / 64);
    gemm64<<<go, 256>>>(pO, Wo, bo, out, M, DIM, INNER);
}

// round 3
// speedup vs baseline: 1.2527x; 1.1159x over previous
#include <cuda_runtime.h>
#include <cstdint>

#define BATCH 2
#define SEQ 2048
#define DIM 512
#define INNER 512
#define N_HEAD 8
#define HEAD_DIM 64
#define ATT_T 1e-4f
#define SCALE_F 0.125f

typedef unsigned long long ull;

// scratch (allocation-free rule: __device__ globals)
__device__ float g_Q[BATCH * SEQ * INNER];
__device__ float g_K[BATCH * SEQ * INNER];
__device__ float g_V[BATCH * SEQ * INNER];
__device__ float g_O[BATCH * SEQ * INNER];

// ---------------- packed f32x2 helpers ---------------------------------
static __device__ __forceinline__ ull pk2(float lo, float hi) {
    ull d;
    asm("mov.b64 %0, {%1, %2};" : "=l"(d)
        : "r"(__float_as_uint(lo)), "r"(__float_as_uint(hi)));
    return d;
}
static __device__ __forceinline__ ull dup2f(float x) {
    ull d;
    unsigned u = __float_as_uint(x);
    asm("mov.b64 %0, {%1, %1};" : "=l"(d) : "r"(u));
    return d;
}
static __device__ __forceinline__ void fma2(ull& d, ull a, ull b) {
    asm("fma.rn.f32x2 %0, %1, %2, %0;" : "+l"(d) : "l"(a), "l"(b));
}
static __device__ __forceinline__ float2 up2(ull v) {
    unsigned lo, hi;
    asm("mov.b64 {%0, %1}, %2;" : "=r"(lo), "=r"(hi) : "l"(v));
    return make_float2(__uint_as_float(lo), __uint_as_float(hi));
}
static __device__ __forceinline__ float psum(ull v) {
    float2 f = up2(v);
    return f.x + f.y;
}

// swizzled float4 store: logical float col c (mult of 4) of `row`, swizzle tag t.
// pair index p = c>>1 (even); dest pairs {p^t, (p^t)^1}; swap halves if t odd.
static __device__ __forceinline__ void st_sw4(float* base, int stride_f,
                                              int row, int c, int t, float4 v) {
    int e = ((c >> 1) ^ t) & ~1;
    if (t & 1) { float x = v.x, y = v.y; v.x = v.z; v.y = v.w; v.z = x; v.w = y; }
    *(float4*)&base[row * stride_f + (e << 1)] = v;
}

// ---------------------------------------------------------------------------
// Tiled fp32 GEMM (FFMA2): C[M,N] = A[M,K] @ B[K,N] (+ bias).
// ---------------------------------------------------------------------------
#define GQS 68
__global__ void __launch_bounds__(256) gemm64(
    const float* __restrict__ A, const float* __restrict__ B,
    const float* __restrict__ bias, float* __restrict__ C,
    int M, int N, int K)
{
    __shared__ float As[16][GQS];
    __shared__ float Bs[16][GQS];

    const int tid = threadIdx.x;
    const int tx = tid & 15, ty = tid >> 4;
    const int bn = blockIdx.x * 64, bm = blockIdx.y * 64;

    ull acc2[4][2];
    #pragma unroll
    for (int i = 0; i < 4; i++) { acc2[i][0] = 0ull; acc2[i][1] = 0ull; }

    for (int kt = 0; kt < K; kt += 16) {
        {
            int r = tid >> 2;
            int c = (tid & 3) << 2;
            float4 v = *(const float4*)&A[(size_t)(bm + r) * K + kt + c];
            As[c + 0][r] = v.x; As[c + 1][r] = v.y;
            As[c + 2][r] = v.z; As[c + 3][r] = v.w;
        }
        {
            int r = tid >> 4;
            int c = (tid & 15) << 2;
            *(float4*)&Bs[r][c] = *(const float4*)&B[(size_t)(kt + r) * N + bn + c];
        }
        __syncthreads();
        #pragma unroll
        for (int k = 0; k < 16; k++) {
            float4 a4 = *(const float4*)&As[k][ty << 2];
            float4 b4 = *(const float4*)&Bs[k][tx << 2];
            ull bp0 = pk2(b4.x, b4.y), bp1 = pk2(b4.z, b4.w);
            float av[4] = {a4.x, a4.y, a4.z, a4.w};
            #pragma unroll
            for (int i = 0; i < 4; i++) {
                ull ad = dup2f(av[i]);
                fma2(acc2[i][0], ad, bp0);
                fma2(acc2[i][1], ad, bp1);
            }
        }
        __syncthreads();
    }

    #pragma unroll
    for (int i = 0; i < 4; i++) {
        int row = bm + (ty << 2) + i;
        int col = bn + (tx << 2);
        float2 p0 = up2(acc2[i][0]), p1 = up2(acc2[i][1]);
        float4 o = {p0.x, p0.y, p1.x, p1.y};
        if (bias) {
            o.x += bias[col]; o.y += bias[col + 1];
            o.z += bias[col + 2]; o.w += bias[col + 3];
        }
        *(float4*)&C[(size_t)row * N + col] = o;
    }
}

// ---------------------------------------------------------------------------
// Attention. Block = (b, h, 128-query tile); 256 thr = 16(ty,q) x 16(tx,k).
// FFMA2 packed over the REDUCTION dim -> both operands are natural LDS.64
// pairs (zero packing movs). Smem layouts (all row-major, XOR pair-swizzle):
//   Qs[q][d] t=q>>3, Ks[k][d] t=k>>3, Vs[d][k] t=d>>2, Ws[q][k] t=q>>3
// ---------------------------------------------------------------------------
#define TQ 128
#define TK 128
#define NKT (SEQ / TK)

__global__ void __launch_bounds__(256, 1) attn_kernel()
{
    extern __shared__ float sm[];
    float* Qs = sm;                     // 128 x 64
    float* Ks = Qs + 128 * 64;          // 128 x 64
    float* Vs = Ks + 128 * 64;          // 64 x 128
    float* Ws = Vs + 64 * 128;          // 128 x 128

    const int tid = threadIdx.x;
    const int tx = tid & 15, ty = tid >> 4;
    const int tx8 = tx << 3, ty8 = ty << 3, tx4 = tx << 2;
    const int qt = blockIdx.x, h = blockIdx.y, b = blockIdx.z;

    const size_t baseQ  = ((size_t)b * SEQ + qt * TQ) * INNER + h * HEAD_DIM;
    const size_t baseKV = ((size_t)b * SEQ) * INNER + h * HEAD_DIM;

    // load Q tile: Qs[q][d], swizzled
    #pragma unroll
    for (int i = 0; i < 8; i++) {
        int idx = tid + 256 * i;
        int row = idx >> 4;               // q 0..127
        int c   = (idx & 15) << 2;        // d
        float4 v = *(const float4*)&g_Q[baseQ + (size_t)row * INNER + c];
        st_sw4(Qs, 64, row, c, (row >> 3) & 15, v);
    }

    float m[8], l[8];
    #pragma unroll
    for (int i = 0; i < 8; i++) { m[i] = -__int_as_float(0x7f800000); l[i] = 0.f; }

    // ---------------- pass 1: online (m, Z) ----------------
    for (int kt = 0; kt < NKT; kt++) {
        __syncthreads();
        #pragma unroll
        for (int i = 0; i < 8; i++) {
            int idx = tid + 256 * i;
            int row = idx >> 4;
            int c   = (idx & 15) << 2;
            float4 v = *(const float4*)&g_K[baseKV + (size_t)(kt * TK + row) * INNER + c];
            st_sw4(Ks, 64, row, c, (row >> 3) & 15, v);
        }
        __syncthreads();

        ull acc2[8][8];
        #pragma unroll
        for (int i = 0; i < 8; i++)
            #pragma unroll
            for (int j = 0; j < 8; j++) acc2[i][j] = 0ull;

        #pragma unroll 4
        for (int dp = 0; dp < 32; dp++) {
            ull q2[8], k2[8];
            int qo = (dp ^ ty) << 1;
            int ko = (dp ^ tx) << 1;
            #pragma unroll
            for (int i = 0; i < 8; i++) q2[i] = *(const ull*)&Qs[(ty8 + i) * 64 + qo];
            #pragma unroll
            for (int j = 0; j < 8; j++) k2[j] = *(const ull*)&Ks[(tx8 + j) * 64 + ko];
            #pragma unroll
            for (int i = 0; i < 8; i++)
                #pragma unroll
                for (int j = 0; j < 8; j++)
                    fma2(acc2[i][j], q2[i], k2[j]);
        }

        #pragma unroll
        for (int qi = 0; qi < 8; qi++) {
            float sv[8];
            #pragma unroll
            for (int j = 0; j < 8; j++) sv[j] = psum(acc2[qi][j]) * SCALE_F;
            float mt = sv[0];
            #pragma unroll
            for (int j = 1; j < 8; j++) mt = fmaxf(mt, sv[j]);
            #pragma unroll
            for (int o = 1; o < 16; o <<= 1)
                mt = fmaxf(mt, __shfl_xor_sync(0xffffffffu, mt, o));
            float mn = fmaxf(m[qi], mt);
            float p = 0.f;
            #pragma unroll
            for (int j = 0; j < 8; j++) p += __expf(sv[j] - mn);
            #pragma unroll
            for (int o = 1; o < 16; o <<= 1)
                p += __shfl_xor_sync(0xffffffffu, p, o);
            l[qi] = l[qi] * __expf(m[qi] - mn) + p;
            m[qi] = mn;
        }
    }

    float thr[8], wsum[8];
    #pragma unroll
    for (int qi = 0; qi < 8; qi++) { thr[qi] = ATT_T * l[qi]; wsum[qi] = 0.f; }

    ull oacc[8][4];
    #pragma unroll
    for (int i = 0; i < 8; i++)
        #pragma unroll
        for (int j = 0; j < 4; j++) oacc[i][j] = 0ull;

    // ---------------- pass 2: weights + O ----------------
    for (int kt = 0; kt < NKT; kt++) {
        __syncthreads();
        #pragma unroll
        for (int i = 0; i < 8; i++) {
            int idx = tid + 256 * i;
            int row = idx >> 4;
            int c   = (idx & 15) << 2;
            size_t goff = baseKV + (size_t)(kt * TK + row) * INNER + c;
            float4 v = *(const float4*)&g_K[goff];
            st_sw4(Ks, 64, row, c, (row >> 3) & 15, v);
            float4 vv = *(const float4*)&g_V[goff];
            // transpose V into Vs[d][k], swizzle t = d>>2 (= c>>2 for all 4)
            int tv = (c >> 2) & 15;
            int pk = row >> 1, lb = row & 1;
            Vs[(c + 0) * 128 + (((pk ^ tv) << 1) | lb)] = vv.x;
            Vs[(c + 1) * 128 + (((pk ^ tv) << 1) | lb)] = vv.y;
            Vs[(c + 2) * 128 + (((pk ^ tv) << 1) | lb)] = vv.z;
            Vs[(c + 3) * 128 + (((pk ^ tv) << 1) | lb)] = vv.w;
        }
        __syncthreads();

        ull acc2[8][8];
        #pragma unroll
        for (int i = 0; i < 8; i++)
            #pragma unroll
            for (int j = 0; j < 8; j++) acc2[i][j] = 0ull;

        #pragma unroll 4
        for (int dp = 0; dp < 32; dp++) {
            ull q2[8], k2[8];
            int qo = (dp ^ ty) << 1;
            int ko = (dp ^ tx) << 1;
            #pragma unroll
            for (int i = 0; i < 8; i++) q2[i] = *(const ull*)&Qs[(ty8 + i) * 64 + qo];
            #pragma unroll
            for (int j = 0; j < 8; j++) k2[j] = *(const ull*)&Ks[(tx8 + j) * 64 + ko];
            #pragma unroll
            for (int i = 0; i < 8; i++)
                #pragma unroll
                for (int j = 0; j < 8; j++)
                    fma2(acc2[i][j], q2[i], k2[j]);
        }

        // weights -> Ws[q][k] (swizzled, t = q>>3 = ty)
        #pragma unroll
        for (int qi = 0; qi < 8; qi++) {
            float w[8];
            #pragma unroll
            for (int j = 0; j < 8; j++) {
                float s = psum(acc2[qi][j]) * SCALE_F;
                w[j] = fmaxf(__expf(s - m[qi]) - thr[qi], 0.f);
                wsum[qi] += w[j];
            }
            int row = ty8 + qi;
            st_sw4(Ws, 128, row, tx8,     ty, make_float4(w[0], w[1], w[2], w[3]));
            st_sw4(Ws, 128, row, tx8 + 4, ty, make_float4(w[4], w[5], w[6], w[7]));
        }
        __syncthreads();

        // PV: oacc[qi][di] += (W pair over k) * (V pair over k)
        #pragma unroll 4
        for (int kp = 0; kp < 64; kp++) {
            ull w2[8], v2[4];
            int wo = (kp ^ ty) << 1;
            int vo = (kp ^ tx) << 1;
            #pragma unroll
            for (int i = 0; i < 8; i++) w2[i] = *(const ull*)&Ws[(ty8 + i) * 128 + wo];
            #pragma unroll
            for (int j = 0; j < 4; j++) v2[j] = *(const ull*)&Vs[(tx4 + j) * 128 + vo];
            #pragma unroll
            for (int i = 0; i < 8; i++)
                #pragma unroll
                for (int j = 0; j < 4; j++)
                    fma2(oacc[i][j], w2[i], v2[j]);
        }
    }

    // reduce wsum across 16 key-lanes, normalize, write O
    #pragma unroll
    for (int qi = 0; qi < 8; qi++) {
        #pragma unroll
        for (int o = 1; o < 16; o <<= 1)
            wsum[qi] += __shfl_xor_sync(0xffffffffu, wsum[qi], o);
        float inv = 1.f / wsum[qi];
        float4 ov = {psum(oacc[qi][0]) * inv, psum(oacc[qi][1]) * inv,
                     psum(oacc[qi][2]) * inv, psum(oacc[qi][3]) * inv};
        *(float4*)&g_O[baseQ + (size_t)(ty8 + qi) * INNER + tx4] = ov;
    }
}

// ---------------------------------------------------------------------------
extern "C" void kernel_launch(void* const* d_in, const int* in_sizes, int n_in,
                              void* d_out, int out_size)
{
    const float* fr = (const float*)d_in[0];
    const float* dt = (const float*)d_in[1];
    const float* Wq = (const float*)d_in[2];
    const float* Wk = (const float*)d_in[3];
    const float* Wv = (const float*)d_in[4];
    const float* Wo = (const float*)d_in[5];
    const float* bo = (const float*)d_in[6];
    float* out = (float*)d_out;

    float *pQ, *pK, *pV, *pO;
    cudaGetSymbolAddress((void**)&pQ, g_Q);
    cudaGetSymbolAddress((void**)&pK, g_K);
    cudaGetSymbolAddress((void**)&pV, g_V);
    cudaGetSymbolAddress((void**)&pO, g_O);

    const int M = BATCH * SEQ;   // 4096

    dim3 gp(INNER / 64, M / 64);
    gemm64<<<gp, 256>>>(fr, Wq, nullptr, pQ, M, INNER, DIM);
    gemm64<<<gp, 256>>>(dt, Wk, nullptr, pK, M, INNER, DIM);
    gemm64<<<gp, 256>>>(dt, Wv, nullptr, pV, M, INNER, DIM);

    const int smem = (128 * 64 * 2 + 64 * 128 + 128 * 128) * (int)sizeof(float); // 163840
    cudaFuncSetAttribute(attn_kernel,
                         cudaFuncAttributeMaxDynamicSharedMemorySize, smem);
    attn_kernel<<<dim3(SEQ / TQ, N_HEAD, BATCH), 256, smem>>>();

    dim3 go(DIM / 64, M / 64);
    gemm64<<<go, 256>>>(pO, Wo, bo, out, M, DIM, INNER);
}

// round 5
// speedup vs baseline: 1.3825x; 1.1036x over previous
#include <cuda_runtime.h>
#include <cstdint>

#define BATCH 2
#define SEQ 2048
#define DIM 512
#define INNER 512
#define N_HEAD 8
#define HEAD_DIM 64
#define ATT_T 1e-4f
#define SCALE_F 0.125f

typedef unsigned long long ull;

// scratch (allocation-free rule: __device__ globals)
__device__ float g_Q[BATCH * SEQ * INNER];
__device__ float g_K[BATCH * SEQ * INNER];
__device__ float g_V[BATCH * SEQ * INNER];
__device__ float g_O[BATCH * SEQ * INNER];
__device__ float g_P[(size_t)BATCH * N_HEAD * SEQ * SEQ];   // exp(scores), 268MB
__device__ float g_Z[BATCH * N_HEAD * SEQ];

// ---------------- packed f32x2 helpers ---------------------------------
static __device__ __forceinline__ void fma2(ull& d, ull a, ull b) {
    asm("fma.rn.f32x2 %0, %1, %2, %0;" : "+l"(d) : "l"(a), "l"(b));
}
static __device__ __forceinline__ float2 up2(ull v) {
    unsigned lo, hi;
    asm("mov.b64 {%0, %1}, %2;" : "=r"(lo), "=r"(hi) : "l"(v));
    return make_float2(__uint_as_float(lo), __uint_as_float(hi));
}
static __device__ __forceinline__ float psum(ull v) {
    float2 f = up2(v);
    return f.x + f.y;
}

// swizzled float4 store: logical float col c (mult of 4) in `row`, tag t.
// pair p -> slot p^t; the float4 = pairs {c>>1, (c>>1)+1}.
static __device__ __forceinline__ void st_sw4(float* base, int stride_f,
                                              int row, int c, int t, float4 v) {
    int e = ((c >> 1) ^ t) & ~1;
    if (t & 1) { float x = v.x, y = v.y; v.x = v.z; v.y = v.w; v.z = x; v.w = y; }
    *(float4*)&base[row * stride_f + (e << 1)] = v;
}

// ---------------------------------------------------------------------------
// gemm128: C[M,N] = A[M,K] @ B[K,N] (+bias). 512 thr, 128x128 tile, BK=64.
// Reduction-packed FFMA2: both operands natural LDS.64 pairs.
// smem: As[m][k] tag m>>3, Bs[n][k] (transposed) tag n>>2.
// ---------------------------------------------------------------------------
__global__ void __launch_bounds__(512, 1) gemm128(
    const float* __restrict__ A, const float* __restrict__ B,
    const float* __restrict__ bias, float* __restrict__ C,
    int M, int N, int K)
{
    extern __shared__ float sm[];
    float* As = sm;              // 128 x 64
    float* Bs = sm + 128 * 64;   // 128 x 64

    const int tid = threadIdx.x;
    const int tx = tid & 31, ty = tid >> 5;
    const int tx4 = tx << 2, ty8 = ty << 3;
    const int bn = blockIdx.x * 128, bm = blockIdx.y * 128;

    ull acc2[8][4];
    #pragma unroll
    for (int i = 0; i < 8; i++)
        #pragma unroll
        for (int j = 0; j < 4; j++) acc2[i][j] = 0ull;

    for (int kc = 0; kc < K; kc += 64) {
        __syncthreads();
        #pragma unroll
        for (int i = 0; i < 4; i++) {                 // A fill
            int idx = tid + 512 * i;
            int row = idx >> 4;                       // m 0..127
            int c   = (idx & 15) << 2;                // k
            float4 v = *(const float4*)&A[(size_t)(bm + row) * K + kc + c];
            st_sw4(As, 64, row, c, row >> 3, v);
        }
        #pragma unroll
        for (int i = 0; i < 4; i++) {                 // B fill (transpose)
            int idx = tid + 512 * i;
            int k   = idx >> 5;                       // 0..63
            int c   = (idx & 31) << 2;                // n 0..124
            float4 v = *(const float4*)&B[(size_t)(kc + k) * N + bn + c];
            int t = c >> 2, pk = k >> 1;
            int sl = ((pk ^ t) << 1) | (k & 1);
            Bs[(c + 0) * 64 + sl] = v.x; Bs[(c + 1) * 64 + sl] = v.y;
            Bs[(c + 2) * 64 + sl] = v.z; Bs[(c + 3) * 64 + sl] = v.w;
        }
        __syncthreads();

        #pragma unroll 4
        for (int dp = 0; dp < 32; dp++) {
            ull a2[8], b2[4];
            int ao = (dp ^ ty) << 1;
            int bo = (dp ^ tx) << 1;
            #pragma unroll
            for (int i = 0; i < 8; i++) a2[i] = *(const ull*)&As[(ty8 + i) * 64 + ao];
            #pragma unroll
            for (int j = 0; j < 4; j++) b2[j] = *(const ull*)&Bs[(tx4 + j) * 64 + bo];
            #pragma unroll
            for (int i = 0; i < 8; i++)
                #pragma unroll
                for (int j = 0; j < 4; j++)
                    fma2(acc2[i][j], a2[i], b2[j]);
        }
    }

    #pragma unroll
    for (int i = 0; i < 8; i++) {
        int row = bm + ty8 + i, col = bn + tx4;
        float4 o = {psum(acc2[i][0]), psum(acc2[i][1]),
                    psum(acc2[i][2]), psum(acc2[i][3])};
        if (bias) {
            o.x += bias[col]; o.y += bias[col + 1];
            o.z += bias[col + 2]; o.w += bias[col + 3];
        }
        *(float4*)&C[(size_t)row * N + col] = o;
    }
}

// ---------------------------------------------------------------------------
// Pass A: S = Q K^T * scale, P = exp(S) -> gmem, Z = row sums -> gmem.
// No max-subtraction needed: |s| bounded (~18), exp safe in fp32.
// Block = (qt 128, h, b), 512 thr, per-thread 8q x 4k.
// ---------------------------------------------------------------------------
__global__ void __launch_bounds__(512, 1) attn_score()
{
    extern __shared__ float sm[];
    float* Qs = sm;              // 128 x 64, tag q>>3
    float* Ks = sm + 128 * 64;   // 128 x 64, tag k>>2

    const int tid = threadIdx.x;
    const int tx = tid & 31, ty = tid >> 5;
    const int tx4 = tx << 2, ty8 = ty << 3;
    const int qt = blockIdx.x, h = blockIdx.y, b = blockIdx.z;

    const size_t baseQ = ((size_t)b * SEQ + qt * 128) * INNER + h * HEAD_DIM;
    const size_t baseK = ((size_t)b * SEQ) * INNER + h * HEAD_DIM;
    const size_t rowP  = ((size_t)(b * N_HEAD + h) * SEQ + qt * 128);

    #pragma unroll
    for (int i = 0; i < 4; i++) {
        int idx = tid + 512 * i;
        int row = idx >> 4;
        int c   = (idx & 15) << 2;
        float4 v = *(const float4*)&g_Q[baseQ + (size_t)row * INNER + c];
        st_sw4(Qs, 64, row, c, row >> 3, v);
    }

    float l[8];
    #pragma unroll
    for (int i = 0; i < 8; i++) l[i] = 0.f;

    for (int kt = 0; kt < SEQ / 128; kt++) {
        __syncthreads();
        #pragma unroll
        for (int i = 0; i < 4; i++) {
            int idx = tid + 512 * i;
            int row = idx >> 4;
            int c   = (idx & 15) << 2;
            float4 v = *(const float4*)&g_K[baseK + (size_t)(kt * 128 + row) * INNER + c];
            st_sw4(Ks, 64, row, c, row >> 2, v);
        }
        __syncthreads();

        ull acc2[8][4];
        #pragma unroll
        for (int i = 0; i < 8; i++)
            #pragma unroll
            for (int j = 0; j < 4; j++) acc2[i][j] = 0ull;

        #pragma unroll 4
        for (int dp = 0; dp < 32; dp++) {
            ull q2[8], k2[4];
            int qo = (dp ^ ty) << 1;
            int ko = (dp ^ tx) << 1;
            #pragma unroll
            for (int i = 0; i < 8; i++) q2[i] = *(const ull*)&Qs[(ty8 + i) * 64 + qo];
            #pragma unroll
            for (int j = 0; j < 4; j++) k2[j] = *(const ull*)&Ks[(tx4 + j) * 64 + ko];
            #pragma unroll
            for (int i = 0; i < 8; i++)
                #pragma unroll
                for (int j = 0; j < 4; j++)
                    fma2(acc2[i][j], q2[i], k2[j]);
        }

        #pragma unroll
        for (int qi = 0; qi < 8; qi++) {
            float4 p;
            p.x = __expf(psum(acc2[qi][0]) * SCALE_F);
            p.y = __expf(psum(acc2[qi][1]) * SCALE_F);
            p.z = __expf(psum(acc2[qi][2]) * SCALE_F);
            p.w = __expf(psum(acc2[qi][3]) * SCALE_F);
            l[qi] += (p.x + p.y) + (p.z + p.w);
            *(float4*)&g_P[(rowP + ty8 + qi) * SEQ + kt * 128 + tx4] = p;
        }
    }

    #pragma unroll
    for (int qi = 0; qi < 8; qi++) {
        float v = l[qi];
        #pragma unroll
        for (int o = 1; o < 32; o <<= 1)
            v += __shfl_xor_sync(0xffffffffu, v, o);
        if (tx == 0)
            g_Z[(b * N_HEAD + h) * SEQ + qt * 128 + ty8 + qi] = v;
    }
}

// ---------------------------------------------------------------------------
// Pass B: w = relu(P - t*Z) (applied during smem fill, with per-row sums),
// O = (w @ V) / rowsum(w). Block = (qt 128, h, b), 256 thr, 8q x 4d each.
// ---------------------------------------------------------------------------
__global__ void __launch_bounds__(256, 2) attn_pv()
{
    extern __shared__ float sm[];
    float* Ws = sm;                    // 128 x 128, tag q>>3
    float* Vs = Ws + 128 * 128;        // 64 x 128 (V^T), tag d>>2
    float* wsumS = Vs + 64 * 128;      // 128
    float* thrS  = wsumS + 128;        // 128

    const int tid = threadIdx.x;
    const int tx = tid & 15, ty = tid >> 4;
    const int tx4 = tx << 2, ty8 = ty << 3;
    const int qt = blockIdx.x, h = blockIdx.y, b = blockIdx.z;

    const size_t baseV = ((size_t)b * SEQ) * INNER + h * HEAD_DIM;
    const size_t baseO = ((size_t)b * SEQ + qt * 128) * INNER + h * HEAD_DIM;
    const size_t rowP  = ((size_t)(b * N_HEAD + h) * SEQ + qt * 128);
    const int    rowZ  = (b * N_HEAD + h) * SEQ + qt * 128;

    if (tid < 128) {
        thrS[tid] = ATT_T * g_Z[rowZ + tid];
        wsumS[tid] = 0.f;
    }

    ull oacc[8][4];
    #pragma unroll
    for (int i = 0; i < 8; i++)
        #pragma unroll
        for (int j = 0; j < 4; j++) oacc[i][j] = 0ull;

    for (int kt = 0; kt < SEQ / 128; kt++) {
        __syncthreads();
        // fill Ws with w = relu(P - thr); accumulate per-row sums.
        // 16 iters x 256 thr x float4 = 16384 floats = full 128x128 tile.
        // row = 8*i + warp  (unique per (i, warp) -> race-free wsumS update)
        #pragma unroll
        for (int i = 0; i < 16; i++) {
            int idx = tid + 256 * i;
            int row = idx >> 5;                 // q row 0..127; const per warp
            int c   = (idx & 31) << 2;          // k col
            float4 p = *(const float4*)&g_P[(rowP + row) * SEQ + kt * 128 + c];
            float t = thrS[row];
            float4 w;
            w.x = fmaxf(p.x - t, 0.f); w.y = fmaxf(p.y - t, 0.f);
            w.z = fmaxf(p.z - t, 0.f); w.w = fmaxf(p.w - t, 0.f);
            float s = (w.x + w.y) + (w.z + w.w);
            #pragma unroll
            for (int o = 16; o > 0; o >>= 1)
                s += __shfl_xor_sync(0xffffffffu, s, o);
            if ((tid & 31) == 0) wsumS[row] += s;
            st_sw4(Ws, 128, row, c, row >> 3, w);
        }
        // fill Vs (transpose)
        #pragma unroll
        for (int i = 0; i < 8; i++) {
            int idx = tid + 256 * i;
            int row = idx >> 4;                 // k 0..127
            int c   = (idx & 15) << 2;          // d
            float4 v = *(const float4*)&g_V[baseV + (size_t)(kt * 128 + row) * INNER + c];
            int t = c >> 2, pk = row >> 1;
            int sl = ((pk ^ t) << 1) | (row & 1);
            Vs[(c + 0) * 128 + sl] = v.x; Vs[(c + 1) * 128 + sl] = v.y;
            Vs[(c + 2) * 128 + sl] = v.z; Vs[(c + 3) * 128 + sl] = v.w;
        }
        __syncthreads();

        #pragma unroll 4
        for (int kp = 0; kp < 64; kp++) {
            ull w2[8], v2[4];
            int wo = (kp ^ ty) << 1;
            int vo = (kp ^ tx) << 1;
            #pragma unroll
            for (int i = 0; i < 8; i++) w2[i] = *(const ull*)&Ws[(ty8 + i) * 128 + wo];
            #pragma unroll
            for (int j = 0; j < 4; j++) v2[j] = *(const ull*)&Vs[(tx4 + j) * 128 + vo];
            #pragma unroll
            for (int i = 0; i < 8; i++)
                #pragma unroll
                for (int j = 0; j < 4; j++)
                    fma2(oacc[i][j], w2[i], v2[j]);
        }
    }

    #pragma unroll
    for (int qi = 0; qi < 8; qi++) {
        float inv = 1.f / wsumS[ty8 + qi];
        float4 ov = {psum(oacc[qi][0]) * inv, psum(oacc[qi][1]) * inv,
                     psum(oacc[qi][2]) * inv, psum(oacc[qi][3]) * inv};
        *(float4*)&g_O[baseO + (size_t)(ty8 + qi) * INNER + tx4] = ov;
    }
}

// ---------------------------------------------------------------------------
extern "C" void kernel_launch(void* const* d_in, const int* in_sizes, int n_in,
                              void* d_out, int out_size)
{
    const float* fr = (const float*)d_in[0];
    const float* dt = (const float*)d_in[1];
    const float* Wq = (const float*)d_in[2];
    const float* Wk = (const float*)d_in[3];
    const float* Wv = (const float*)d_in[4];
    const float* Wo = (const float*)d_in[5];
    const float* bo = (const float*)d_in[6];
    float* out = (float*)d_out;

    float *pQ, *pK, *pV, *pO;
    cudaGetSymbolAddress((void**)&pQ, g_Q);
    cudaGetSymbolAddress((void**)&pK, g_K);
    cudaGetSymbolAddress((void**)&pV, g_V);
    cudaGetSymbolAddress((void**)&pO, g_O);

    const int M = BATCH * SEQ;   // 4096

    const int smG = 128 * 64 * 2 * (int)sizeof(float);                  // 64KB
    const int smA = 128 * 64 * 2 * (int)sizeof(float);                  // 64KB
    const int smB = (128 * 128 + 64 * 128 + 256) * (int)sizeof(float);  // ~97KB
    cudaFuncSetAttribute(gemm128,    cudaFuncAttributeMaxDynamicSharedMemorySize, smG);
    cudaFuncSetAttribute(attn_score, cudaFuncAttributeMaxDynamicSharedMemorySize, smA);
    cudaFuncSetAttribute(attn_pv,    cudaFuncAttributeMaxDynamicSharedMemorySize, smB);

    dim3 gp(INNER / 128, M / 128);
    gemm128<<<gp, 512, smG>>>(fr, Wq, nullptr, pQ, M, INNER, DIM);
    gemm128<<<gp, 512, smG>>>(dt, Wk, nullptr, pK, M, INNER, DIM);
    gemm128<<<gp, 512, smG>>>(dt, Wv, nullptr, pV, M, INNER, DIM);

    attn_score<<<dim3(SEQ / 128, N_HEAD, BATCH), 512, smA>>>();
    attn_pv<<<dim3(SEQ / 128, N_HEAD, BATCH), 256, smB>>>();

    dim3 go(DIM / 128, M / 128);
    gemm128<<<go, 512, smG>>>(pO, Wo, bo, out, M, DIM, INNER);
}